// round 16
// baseline (speedup 1.0000x reference)
#include <cuda_runtime.h>
#include <cuda_fp16.h>

#define NN 100000
#define NE 1000000
#define D  64
#define HS 68              // smem h-row stride (floats)
#define SCAN_BS 1024
#define NBLK 98            // ceil(NN/1024)

// ---------------- static scratch ----------------
__device__ __half2 g_bufA[NN * (D / 2)];
__device__ __half2 g_bufB[NN * (D / 2)];
__device__ float g_out_norm[NN];
__device__ float g_in_norm[NN];
__device__ int   g_deg_out[NN];
__device__ int   g_deg_in[NN];
__device__ int   g_row_start[NN];
__device__ int   g_fill[NN];
__device__ int   g_src_sorted[NE + 4];   // +4: unclamped prefetch tail
__device__ int   g_bsum[NBLK];

// ---------------- helpers ----------------
__device__ __forceinline__ unsigned long long pk2(float lo, float hi) {
    unsigned long long r;
    asm("mov.b64 %0, {%1,%2};" : "=l"(r) : "f"(lo), "f"(hi));
    return r;
}
__device__ __forceinline__ void fma2(unsigned long long& d,
                                     unsigned long long a, unsigned long long b) {
    asm("fma.rn.f32x2 %0, %1, %2, %0;" : "+l"(d) : "l"(a), "l"(b));
}
__device__ __forceinline__ float2 upk2(unsigned long long v) {
    float2 f;
    asm("mov.b64 {%0,%1}, %2;" : "=f"(f.x), "=f"(f.y) : "l"(v));
    return f;
}
__device__ __forceinline__ float2 h2f(unsigned int u) {
    float2 f;
    asm("{\n\t"
        ".reg .f16 lo, hi;\n\t"
        "mov.b32 {lo, hi}, %2;\n\t"
        "cvt.f32.f16 %0, lo;\n\t"
        "cvt.f32.f16 %1, hi;\n\t"
        "}"
        : "=f"(f.x), "=f"(f.y) : "r"(u));
    return f;
}
__device__ __forceinline__ unsigned int f2h(float a, float b) {
    unsigned int u;
    asm("{\n\t"
        ".reg .f16 lo, hi;\n\t"
        "cvt.rn.f16.f32 lo, %1;\n\t"
        "cvt.rn.f16.f32 hi, %2;\n\t"
        "mov.b32 %0, {lo, hi};\n\t"
        "}"
        : "=r"(u) : "f"(a), "f"(b));
    return u;
}
__device__ __forceinline__ void addrow(float* acc, uint4 r) {
    float2 f;
    f = h2f(r.x); acc[0] += f.x; acc[1] += f.y;
    f = h2f(r.y); acc[2] += f.x; acc[3] += f.y;
    f = h2f(r.z); acc[4] += f.x; acc[5] += f.y;
    f = h2f(r.w); acc[6] += f.x; acc[7] += f.y;
}

// ---------------- setup kernels ----------------
__global__ void zero_deg_kernel() {
    int i = blockIdx.x * blockDim.x + threadIdx.x;
    if (i < NN / 4) {
        int4 z = make_int4(0, 0, 0, 0);
        reinterpret_cast<int4*>(g_deg_out)[i] = z;
        reinterpret_cast<int4*>(g_deg_in)[i] = z;
    }
}

__global__ void count_kernel(const int4* __restrict__ src4,
                             const int4* __restrict__ dst4) {
    int i = blockIdx.x * blockDim.x + threadIdx.x;
    if (i < NE / 4) {
        int4 s = __ldg(&src4[i]);
        int4 d = __ldg(&dst4[i]);
        atomicAdd(&g_deg_out[s.x], 1); atomicAdd(&g_deg_in[d.x], 1);
        atomicAdd(&g_deg_out[s.y], 1); atomicAdd(&g_deg_in[d.y], 1);
        atomicAdd(&g_deg_out[s.z], 1); atomicAdd(&g_deg_in[d.z], 1);
        atomicAdd(&g_deg_out[s.w], 1); atomicAdd(&g_deg_in[d.w], 1);
    }
}

// block-level scan of deg_in, warp-shuffle based
__global__ void scan1_kernel() {
    __shared__ int swarp[32];
    int t = threadIdx.x;
    int lane = t & 31, wid = t >> 5;
    int i = blockIdx.x * SCAN_BS + t;
    int v = (i < NN) ? g_deg_in[i] : 0;
    int x = v;
#pragma unroll
    for (int off = 1; off < 32; off <<= 1) {
        int n = __shfl_up_sync(0xffffffffu, x, off);
        if (lane >= off) x += n;
    }
    if (lane == 31) swarp[wid] = x;
    __syncthreads();
    if (wid == 0) {
        int w = (lane < 32) ? swarp[lane] : 0;
#pragma unroll
        for (int off = 1; off < 32; off <<= 1) {
            int n = __shfl_up_sync(0xffffffffu, w, off);
            if (lane >= off) w += n;
        }
        swarp[lane] = w;
    }
    __syncthreads();
    int base = (wid == 0) ? 0 : swarp[wid - 1];
    int incl = base + x;
    if (i < NN) g_row_start[i] = incl - v;     // exclusive within block
    if (t == SCAN_BS - 1) g_bsum[blockIdx.x] = incl;
}

// finalize row offsets + fill cursors + norms + PRESCALE x (fused)
__global__ void scan3_kernel(const float4* __restrict__ x) {
    __shared__ int s[128];
    int t = threadIdx.x;
    if (t < 128) s[t] = (t < NBLK) ? g_bsum[t] : 0;
    __syncthreads();
#pragma unroll
    for (int off = 1; off < 128; off <<= 1) {
        int xv = (t >= off && t < 128) ? s[t - off] : 0;
        __syncthreads();
        if (t < 128) s[t] += xv;
        __syncthreads();
    }
    int i = blockIdx.x * blockDim.x + t;
    if (i < NN) {
        int blk = i >> 10;
        int boff = (blk == 0) ? 0 : s[blk - 1];
        int rs = g_row_start[i] + boff;
        g_row_start[i] = rs;
        g_fill[i] = rs;
        int dout = g_deg_out[i]; if (dout < 1) dout = 1;
        int din  = g_deg_in[i];  if (din  < 1) din  = 1;
        float onrm = rsqrtf((float)dout);
        g_out_norm[i] = onrm;
        g_in_norm[i]  = rsqrtf((float)din);
        // prescale this node's feature row: bufA = fp16(x * out_norm)
        const float4* xr = &x[i * 16];
        uint2* br = reinterpret_cast<uint2*>(g_bufA) + i * 16;
#pragma unroll
        for (int q = 0; q < 16; q++) {
            float4 v = __ldg(&xr[q]);
            uint2 st;
            st.x = f2h(v.x * onrm, v.y * onrm);
            st.y = f2h(v.z * onrm, v.w * onrm);
            br[q] = st;
        }
    }
}

__global__ void fill_kernel(const int4* __restrict__ src4,
                            const int4* __restrict__ dst4) {
    int i = blockIdx.x * blockDim.x + threadIdx.x;
    if (i < NE / 4) {
        int4 s = __ldg(&src4[i]);
        int4 d = __ldg(&dst4[i]);
        int p;
        p = atomicAdd(&g_fill[d.x], 1); g_src_sorted[p] = s.x;
        p = atomicAdd(&g_fill[d.y], 1); g_src_sorted[p] = s.y;
        p = atomicAdd(&g_fill[d.z], 1); g_src_sorted[p] = s.z;
        p = atomicAdd(&g_fill[d.w], 1); g_src_sorted[p] = s.w;
    }
}

// ---------------- fused gather + GEMM layer (R12-proven geometry) ----------------
// 256 threads, 64 nodes/block.
// Phase 1: 8-lane group, 2 sequential nodes, pipelined 4x-unrolled gather.
// Phase 2: 8 warps x 8 nodes FFMA2 GEMM; W read as one LDS.128 per k.
__global__ void __launch_bounds__(256) layer_kernel(
        int in_sel, float* __restrict__ out_ext, int out_sel,
        const float* __restrict__ W, const float* __restrict__ b,
        int relu, int scale_out) {
    __shared__ float sW[D * D];      // 16KB
    __shared__ float sh[64 * HS];    // 17.4KB
    __shared__ float sb[D];

    int tid = threadIdx.x;
    int n0 = blockIdx.x * 64;
    for (int i = tid; i < D * D; i += 256) sW[i] = W[i];
    if (tid < D) sb[tid] = b[tid];

    const __half2* in = in_sel ? g_bufB : g_bufA;
    __half2* out_h16 = out_sel ? g_bufB : g_bufA;

    // ---- phase 1: aggregation ----
    {
        const uint4* inp = reinterpret_cast<const uint4*>(in);
        int g  = tid >> 3;
        int c8 = tid & 7;

#pragma unroll
        for (int s = 0; s < 2; s++) {
            int gslot = g * 2 + s;
            int node = n0 + gslot;
            float acc[8];
#pragma unroll
            for (int j = 0; j < 8; j++) acc[j] = 0.f;

            if (node < NN) {
                int e = g_row_start[node];
                int eend = e + g_deg_in[node];
                int i0 = g_src_sorted[e + 0];
                int i1 = g_src_sorted[e + 1];
                int i2 = g_src_sorted[e + 2];
                int i3 = g_src_sorted[e + 3];
                while (e + 3 < eend) {
                    uint4 r0 = __ldg(&inp[i0 * 8 + c8]);
                    uint4 r1 = __ldg(&inp[i1 * 8 + c8]);
                    uint4 r2 = __ldg(&inp[i2 * 8 + c8]);
                    uint4 r3 = __ldg(&inp[i3 * 8 + c8]);
                    e += 4;
                    i0 = g_src_sorted[e + 0];
                    i1 = g_src_sorted[e + 1];
                    i2 = g_src_sorted[e + 2];
                    i3 = g_src_sorted[e + 3];
                    addrow(acc, r0);
                    addrow(acc, r1);
                    addrow(acc, r2);
                    addrow(acc, r3);
                }
                if (e < eend)     { uint4 r = __ldg(&inp[i0 * 8 + c8]); addrow(acc, r); }
                if (e + 1 < eend) { uint4 r = __ldg(&inp[i1 * 8 + c8]); addrow(acc, r); }
                if (e + 2 < eend) { uint4 r = __ldg(&inp[i2 * 8 + c8]); addrow(acc, r); }
                float nrm = g_in_norm[node];
#pragma unroll
                for (int j = 0; j < 8; j++) acc[j] *= nrm;
            }
            float* dstp = &sh[gslot * HS + c8 * 8];
            *reinterpret_cast<float4*>(dstp) =
                make_float4(acc[0], acc[1], acc[2], acc[3]);
            *reinterpret_cast<float4*>(dstp + 4) =
                make_float4(acc[4], acc[5], acc[6], acc[7]);
        }
    }
    __syncthreads();

    // ---- phase 2: GEMM (8 warps x 8 nodes, FFMA2, LDS.128 W) ----
    {
        int w = tid >> 5;
        int lane = tid & 31;
        int r0 = lane >> 4;       // 0/1
        int c2 = lane & 15;       // output col quad
        unsigned long long acc01[4], acc23[4];
#pragma unroll
        for (int m = 0; m < 4; m++) { acc01[m] = 0ull; acc23[m] = 0ull; }

#pragma unroll
        for (int kb = 0; kb < 16; kb++) {
            float4 a4[4];
#pragma unroll
            for (int m = 0; m < 4; m++)
                a4[m] = *reinterpret_cast<const float4*>(
                    &sh[(w * 8 + r0 + 2 * m) * HS + kb * 4]);
#pragma unroll
            for (int q = 0; q < 4; q++) {
                int k = kb * 4 + q;
                ulonglong2 wq = *reinterpret_cast<const ulonglong2*>(
                    &sW[k * D + c2 * 4]);          // one LDS.128: w01 | w23
#pragma unroll
                for (int m = 0; m < 4; m++) {
                    float a = (q == 0) ? a4[m].x : (q == 1) ? a4[m].y
                             : (q == 2) ? a4[m].z : a4[m].w;
                    unsigned long long aa = pk2(a, a);
                    fma2(acc01[m], aa, wq.x);
                    fma2(acc23[m], aa, wq.y);
                }
            }
        }
        float b0 = sb[c2 * 4 + 0], b1 = sb[c2 * 4 + 1];
        float b2 = sb[c2 * 4 + 2], b3 = sb[c2 * 4 + 3];
#pragma unroll
        for (int m = 0; m < 4; m++) {
            int nd = n0 + w * 8 + r0 + 2 * m;
            if (nd < NN) {
                float2 v01 = upk2(acc01[m]);
                float2 v23 = upk2(acc23[m]);
                float o0 = v01.x + b0, o1 = v01.y + b1;
                float o2 = v23.x + b2, o3 = v23.y + b3;
                if (relu) {
                    o0 = fmaxf(o0, 0.f); o1 = fmaxf(o1, 0.f);
                    o2 = fmaxf(o2, 0.f); o3 = fmaxf(o3, 0.f);
                }
                if (scale_out) {
                    float on = g_out_norm[nd];
                    o0 *= on; o1 *= on; o2 *= on; o3 *= on;
                }
                if (out_ext) {
                    reinterpret_cast<float4*>(out_ext)[nd * 16 + c2] =
                        make_float4(o0, o1, o2, o3);
                } else {
                    uint2 st;
                    st.x = f2h(o0, o1);
                    st.y = f2h(o2, o3);
                    reinterpret_cast<uint2*>(out_h16)[nd * 16 + c2] = st;
                }
            }
        }
    }
}

// ---------------- launch ----------------
extern "C" void kernel_launch(void* const* d_in, const int* in_sizes, int n_in,
                              void* d_out, int out_size) {
    const float* x   = (const float*)d_in[0];
    const int*   src = (const int*)d_in[1];
    const int*   dst = (const int*)d_in[2];
    const float* W1  = (const float*)d_in[3];
    const float* b1  = (const float*)d_in[4];
    const float* W2  = (const float*)d_in[5];
    const float* b2  = (const float*)d_in[6];
    const float* W3  = (const float*)d_in[7];
    const float* b3  = (const float*)d_in[8];
    float* out = (float*)d_out;

    const int TB = 256;
    const int GN = (NN + TB - 1) / TB;
    const int GE4 = (NE / 4 + TB - 1) / TB;

    zero_deg_kernel<<<(NN / 4 + TB - 1) / TB, TB>>>();
    count_kernel<<<GE4, TB>>>(reinterpret_cast<const int4*>(src),
                              reinterpret_cast<const int4*>(dst));
    scan1_kernel<<<NBLK, SCAN_BS>>>();
    scan3_kernel<<<GN, TB>>>(reinterpret_cast<const float4*>(x));  // + prescale
    fill_kernel<<<GE4, TB>>>(reinterpret_cast<const int4*>(src),
                             reinterpret_cast<const int4*>(dst));

    const int GL = (NN + 63) / 64;    // 1563
    layer_kernel<<<GL, 256>>>(0, nullptr, 1, W1, b1, 1, 1);   // bufA -> bufB
    layer_kernel<<<GL, 256>>>(1, nullptr, 0, W2, b2, 1, 1);   // bufB -> bufA
    layer_kernel<<<GL, 256>>>(0, out, 0, W3, b3, 0, 0);       // bufA -> out
}

// round 17
// speedup vs baseline: 1.0527x; 1.0527x over previous
#include <cuda_runtime.h>
#include <cuda_fp16.h>

#define NN 100000
#define NE 1000000
#define D  64
#define HS 68              // smem h-row stride (floats)
#define SCAN_BS 1024
#define NBLK 98            // ceil(NN/1024)

// ---------------- static scratch ----------------
__device__ __half2 g_bufA[NN * (D / 2)];
__device__ __half2 g_bufB[NN * (D / 2)];
__device__ float g_out_norm[NN];
__device__ float g_in_norm[NN];
__device__ int   g_deg_out[NN];
__device__ int   g_deg_in[NN];
__device__ int   g_row_start[NN];
__device__ int   g_fill[NN];
__device__ int   g_src_sorted[NE + 4];   // +4: unclamped prefetch tail
__device__ int   g_bsum[NBLK];

// ---------------- helpers ----------------
__device__ __forceinline__ unsigned long long pk2(float lo, float hi) {
    unsigned long long r;
    asm("mov.b64 %0, {%1,%2};" : "=l"(r) : "f"(lo), "f"(hi));
    return r;
}
__device__ __forceinline__ void fma2(unsigned long long& d,
                                     unsigned long long a, unsigned long long b) {
    asm("fma.rn.f32x2 %0, %1, %2, %0;" : "+l"(d) : "l"(a), "l"(b));
}
__device__ __forceinline__ float2 upk2(unsigned long long v) {
    float2 f;
    asm("mov.b64 {%0,%1}, %2;" : "=f"(f.x), "=f"(f.y) : "l"(v));
    return f;
}
__device__ __forceinline__ float2 h2f(unsigned int u) {
    float2 f;
    asm("{\n\t"
        ".reg .f16 lo, hi;\n\t"
        "mov.b32 {lo, hi}, %2;\n\t"
        "cvt.f32.f16 %0, lo;\n\t"
        "cvt.f32.f16 %1, hi;\n\t"
        "}"
        : "=f"(f.x), "=f"(f.y) : "r"(u));
    return f;
}
__device__ __forceinline__ unsigned int f2h(float a, float b) {
    unsigned int u;
    asm("{\n\t"
        ".reg .f16 lo, hi;\n\t"
        "cvt.rn.f16.f32 lo, %1;\n\t"
        "cvt.rn.f16.f32 hi, %2;\n\t"
        "mov.b32 %0, {lo, hi};\n\t"
        "}"
        : "=r"(u) : "f"(a), "f"(b));
    return u;
}
__device__ __forceinline__ void addrow(float* acc, uint4 r) {
    float2 f;
    f = h2f(r.x); acc[0] += f.x; acc[1] += f.y;
    f = h2f(r.y); acc[2] += f.x; acc[3] += f.y;
    f = h2f(r.z); acc[4] += f.x; acc[5] += f.y;
    f = h2f(r.w); acc[6] += f.x; acc[7] += f.y;
}

// ---------------- setup kernels ----------------
__global__ void zero_deg_kernel() {
    int i = blockIdx.x * blockDim.x + threadIdx.x;
    if (i < NN / 4) {
        int4 z = make_int4(0, 0, 0, 0);
        reinterpret_cast<int4*>(g_deg_out)[i] = z;
        reinterpret_cast<int4*>(g_deg_in)[i] = z;
    }
}

__global__ void count_kernel(const int4* __restrict__ src4,
                             const int4* __restrict__ dst4) {
    int i = blockIdx.x * blockDim.x + threadIdx.x;
    if (i < NE / 4) {
        int4 s = __ldg(&src4[i]);
        int4 d = __ldg(&dst4[i]);
        atomicAdd(&g_deg_out[s.x], 1); atomicAdd(&g_deg_in[d.x], 1);
        atomicAdd(&g_deg_out[s.y], 1); atomicAdd(&g_deg_in[d.y], 1);
        atomicAdd(&g_deg_out[s.z], 1); atomicAdd(&g_deg_in[d.z], 1);
        atomicAdd(&g_deg_out[s.w], 1); atomicAdd(&g_deg_in[d.w], 1);
    }
}

// block-level scan of deg_in, warp-shuffle based
__global__ void scan1_kernel() {
    __shared__ int swarp[32];
    int t = threadIdx.x;
    int lane = t & 31, wid = t >> 5;
    int i = blockIdx.x * SCAN_BS + t;
    int v = (i < NN) ? g_deg_in[i] : 0;
    int x = v;
#pragma unroll
    for (int off = 1; off < 32; off <<= 1) {
        int n = __shfl_up_sync(0xffffffffu, x, off);
        if (lane >= off) x += n;
    }
    if (lane == 31) swarp[wid] = x;
    __syncthreads();
    if (wid == 0) {
        int w = (lane < 32) ? swarp[lane] : 0;
#pragma unroll
        for (int off = 1; off < 32; off <<= 1) {
            int n = __shfl_up_sync(0xffffffffu, w, off);
            if (lane >= off) w += n;
        }
        swarp[lane] = w;
    }
    __syncthreads();
    int base = (wid == 0) ? 0 : swarp[wid - 1];
    int incl = base + x;
    if (i < NN) g_row_start[i] = incl - v;     // exclusive within block
    if (t == SCAN_BS - 1) g_bsum[blockIdx.x] = incl;
}

// finalize row offsets + fill cursors + degree norms
__global__ void scan3_kernel() {
    __shared__ int s[128];
    int t = threadIdx.x;
    if (t < 128) s[t] = (t < NBLK) ? g_bsum[t] : 0;
    __syncthreads();
#pragma unroll
    for (int off = 1; off < 128; off <<= 1) {
        int xv = (t >= off && t < 128) ? s[t - off] : 0;
        __syncthreads();
        if (t < 128) s[t] += xv;
        __syncthreads();
    }
    int i = blockIdx.x * blockDim.x + t;
    if (i < NN) {
        int blk = i >> 10;
        int boff = (blk == 0) ? 0 : s[blk - 1];
        int rs = g_row_start[i] + boff;
        g_row_start[i] = rs;
        g_fill[i] = rs;
        int dout = g_deg_out[i]; if (dout < 1) dout = 1;
        int din  = g_deg_in[i];  if (din  < 1) din  = 1;
        g_out_norm[i] = rsqrtf((float)dout);
        g_in_norm[i]  = rsqrtf((float)din);
    }
}

__global__ void fill_kernel(const int4* __restrict__ src4,
                            const int4* __restrict__ dst4) {
    int i = blockIdx.x * blockDim.x + threadIdx.x;
    if (i < NE / 4) {
        int4 s = __ldg(&src4[i]);
        int4 d = __ldg(&dst4[i]);
        int p;
        p = atomicAdd(&g_fill[d.x], 1); g_src_sorted[p] = s.x;
        p = atomicAdd(&g_fill[d.y], 1); g_src_sorted[p] = s.y;
        p = atomicAdd(&g_fill[d.z], 1); g_src_sorted[p] = s.z;
        p = atomicAdd(&g_fill[d.w], 1); g_src_sorted[p] = s.w;
    }
}

// xs = fp16( x * out_norm[row] ) into bufA  (coalesced: thread-per-float4)
__global__ void prescale_kernel(const float4* __restrict__ x) {
    int i = blockIdx.x * blockDim.x + threadIdx.x;
    if (i < NN * (D / 4)) {
        float s = g_out_norm[i >> 4];
        float4 v = __ldg(&x[i]);
        uint2 st;
        st.x = f2h(v.x * s, v.y * s);
        st.y = f2h(v.z * s, v.w * s);
        reinterpret_cast<uint2*>(g_bufA)[i] = st;
    }
}

// ---------------- fused gather + GEMM layer (R12-proven geometry) ----------------
// 256 threads, 64 nodes/block.
// Phase 1: 8-lane group, 2 sequential nodes, pipelined 4x-unrolled gather.
// Phase 2: 8 warps x 8 nodes FFMA2 GEMM; W read as one LDS.128 per k.
__global__ void __launch_bounds__(256) layer_kernel(
        int in_sel, float* __restrict__ out_ext, int out_sel,
        const float* __restrict__ W, const float* __restrict__ b,
        int relu, int scale_out) {
    __shared__ float sW[D * D];      // 16KB
    __shared__ float sh[64 * HS];    // 17.4KB
    __shared__ float sb[D];

    int tid = threadIdx.x;
    int n0 = blockIdx.x * 64;
    for (int i = tid; i < D * D; i += 256) sW[i] = W[i];
    if (tid < D) sb[tid] = b[tid];

    const __half2* in = in_sel ? g_bufB : g_bufA;
    __half2* out_h16 = out_sel ? g_bufB : g_bufA;

    // ---- phase 1: aggregation ----
    {
        const uint4* inp = reinterpret_cast<const uint4*>(in);
        int g  = tid >> 3;
        int c8 = tid & 7;

#pragma unroll
        for (int s = 0; s < 2; s++) {
            int gslot = g * 2 + s;
            int node = n0 + gslot;
            float acc[8];
#pragma unroll
            for (int j = 0; j < 8; j++) acc[j] = 0.f;

            if (node < NN) {
                int e = g_row_start[node];
                int eend = e + g_deg_in[node];
                int i0 = g_src_sorted[e + 0];
                int i1 = g_src_sorted[e + 1];
                int i2 = g_src_sorted[e + 2];
                int i3 = g_src_sorted[e + 3];
                while (e + 3 < eend) {
                    uint4 r0 = __ldg(&inp[i0 * 8 + c8]);
                    uint4 r1 = __ldg(&inp[i1 * 8 + c8]);
                    uint4 r2 = __ldg(&inp[i2 * 8 + c8]);
                    uint4 r3 = __ldg(&inp[i3 * 8 + c8]);
                    e += 4;
                    i0 = g_src_sorted[e + 0];
                    i1 = g_src_sorted[e + 1];
                    i2 = g_src_sorted[e + 2];
                    i3 = g_src_sorted[e + 3];
                    addrow(acc, r0);
                    addrow(acc, r1);
                    addrow(acc, r2);
                    addrow(acc, r3);
                }
                if (e < eend)     { uint4 r = __ldg(&inp[i0 * 8 + c8]); addrow(acc, r); }
                if (e + 1 < eend) { uint4 r = __ldg(&inp[i1 * 8 + c8]); addrow(acc, r); }
                if (e + 2 < eend) { uint4 r = __ldg(&inp[i2 * 8 + c8]); addrow(acc, r); }
                float nrm = g_in_norm[node];
#pragma unroll
                for (int j = 0; j < 8; j++) acc[j] *= nrm;
            }
            float* dstp = &sh[gslot * HS + c8 * 8];
            *reinterpret_cast<float4*>(dstp) =
                make_float4(acc[0], acc[1], acc[2], acc[3]);
            *reinterpret_cast<float4*>(dstp + 4) =
                make_float4(acc[4], acc[5], acc[6], acc[7]);
        }
    }
    __syncthreads();

    // ---- phase 2: GEMM (8 warps x 8 nodes, FFMA2, LDS.128 W) ----
    {
        int w = tid >> 5;
        int lane = tid & 31;
        int r0 = lane >> 4;       // 0/1
        int c2 = lane & 15;       // output col quad
        unsigned long long acc01[4], acc23[4];
#pragma unroll
        for (int m = 0; m < 4; m++) { acc01[m] = 0ull; acc23[m] = 0ull; }

#pragma unroll
        for (int kb = 0; kb < 16; kb++) {
            float4 a4[4];
#pragma unroll
            for (int m = 0; m < 4; m++)
                a4[m] = *reinterpret_cast<const float4*>(
                    &sh[(w * 8 + r0 + 2 * m) * HS + kb * 4]);
#pragma unroll
            for (int q = 0; q < 4; q++) {
                int k = kb * 4 + q;
                ulonglong2 wq = *reinterpret_cast<const ulonglong2*>(
                    &sW[k * D + c2 * 4]);          // one LDS.128: w01 | w23
#pragma unroll
                for (int m = 0; m < 4; m++) {
                    float a = (q == 0) ? a4[m].x : (q == 1) ? a4[m].y
                             : (q == 2) ? a4[m].z : a4[m].w;
                    unsigned long long aa = pk2(a, a);
                    fma2(acc01[m], aa, wq.x);
                    fma2(acc23[m], aa, wq.y);
                }
            }
        }
        float b0 = sb[c2 * 4 + 0], b1 = sb[c2 * 4 + 1];
        float b2 = sb[c2 * 4 + 2], b3 = sb[c2 * 4 + 3];
#pragma unroll
        for (int m = 0; m < 4; m++) {
            int nd = n0 + w * 8 + r0 + 2 * m;
            if (nd < NN) {
                float2 v01 = upk2(acc01[m]);
                float2 v23 = upk2(acc23[m]);
                float o0 = v01.x + b0, o1 = v01.y + b1;
                float o2 = v23.x + b2, o3 = v23.y + b3;
                if (relu) {
                    o0 = fmaxf(o0, 0.f); o1 = fmaxf(o1, 0.f);
                    o2 = fmaxf(o2, 0.f); o3 = fmaxf(o3, 0.f);
                }
                if (scale_out) {
                    float on = g_out_norm[nd];
                    o0 *= on; o1 *= on; o2 *= on; o3 *= on;
                }
                if (out_ext) {
                    reinterpret_cast<float4*>(out_ext)[nd * 16 + c2] =
                        make_float4(o0, o1, o2, o3);
                } else {
                    uint2 st;
                    st.x = f2h(o0, o1);
                    st.y = f2h(o2, o3);
                    reinterpret_cast<uint2*>(out_h16)[nd * 16 + c2] = st;
                }
            }
        }
    }
}

// ---------------- launch ----------------
extern "C" void kernel_launch(void* const* d_in, const int* in_sizes, int n_in,
                              void* d_out, int out_size) {
    const float* x   = (const float*)d_in[0];
    const int*   src = (const int*)d_in[1];
    const int*   dst = (const int*)d_in[2];
    const float* W1  = (const float*)d_in[3];
    const float* b1  = (const float*)d_in[4];
    const float* W2  = (const float*)d_in[5];
    const float* b2  = (const float*)d_in[6];
    const float* W3  = (const float*)d_in[7];
    const float* b3  = (const float*)d_in[8];
    float* out = (float*)d_out;

    const int TB = 256;
    const int GN = (NN + TB - 1) / TB;
    const int GE4 = (NE / 4 + TB - 1) / TB;

    zero_deg_kernel<<<(NN / 4 + TB - 1) / TB, TB>>>();
    count_kernel<<<GE4, TB>>>(reinterpret_cast<const int4*>(src),
                              reinterpret_cast<const int4*>(dst));
    scan1_kernel<<<NBLK, SCAN_BS>>>();
    scan3_kernel<<<GN, TB>>>();
    fill_kernel<<<GE4, TB>>>(reinterpret_cast<const int4*>(src),
                             reinterpret_cast<const int4*>(dst));
    prescale_kernel<<<(NN * 16 + TB - 1) / TB, TB>>>(
        reinterpret_cast<const float4*>(x));

    const int GL = (NN + 63) / 64;    // 1563
    layer_kernel<<<GL, 256>>>(0, nullptr, 1, W1, b1, 1, 1);   // bufA -> bufB
    layer_kernel<<<GL, 256>>>(1, nullptr, 0, W2, b2, 1, 1);   // bufB -> bufA
    layer_kernel<<<GL, 256>>>(0, out, 0, W3, b3, 0, 0);       // bufA -> out
}